// round 3
// baseline (speedup 1.0000x reference)
#include <cuda_runtime.h>
#include <cuda_bf16.h>
#include <cstdint>

// GraphAttentionPooling — persistent grid-stride version.
//   x: [B=196608, F=256] f32, G=65536 groups of P=3 rows.
//   out[g,f] = sum_p softmax_p(dot(x[g,p,:],w))[p] * x[g,p,f]
//
// One warp per group per iteration. Persistent grid (148 SMs x 3 CTAs), each
// warp loops over groups with stride = total warps, double-buffering the 6
// LDG.128s of the NEXT group before computing the current one, so the DRAM
// request stream never goes idle (fixes the 75%-busy duty-cycle gap).

#define F 256
#define P 3
#define F4 (F / 4)            // 64 float4 per row
#define WARPS_PER_BLOCK 8
#define THREADS (WARPS_PER_BLOCK * 32)
#define NUM_SMS 148
#define CTAS_PER_SM 3
#define GRID (NUM_SMS * CTAS_PER_SM)

__global__ __launch_bounds__(THREADS, CTAS_PER_SM)
void gap_kernel(const float* __restrict__ x,
                const float* __restrict__ w,
                float* __restrict__ out,
                int G)
{
    const int lane   = threadIdx.x & 31;
    const int stride = gridDim.x * WARPS_PER_BLOCK;
    int gid = blockIdx.x * WARPS_PER_BLOCK + (threadIdx.x >> 5);

    const float4* __restrict__ w4 = reinterpret_cast<const float4*>(w);
    const float4 w0 = __ldg(&w4[lane]);
    const float4 w1 = __ldg(&w4[lane + 32]);

    if (gid >= G) return;

    const float4* __restrict__ x4 = reinterpret_cast<const float4*>(x);

    float4 cur[6], nxt[6];
    {
        const float4* __restrict__ xr = x4 + (size_t)gid * (size_t)(P * F4);
        cur[0] = __ldcs(&xr[0 * F4 + lane]);
        cur[1] = __ldcs(&xr[0 * F4 + lane + 32]);
        cur[2] = __ldcs(&xr[1 * F4 + lane]);
        cur[3] = __ldcs(&xr[1 * F4 + lane + 32]);
        cur[4] = __ldcs(&xr[2 * F4 + lane]);
        cur[5] = __ldcs(&xr[2 * F4 + lane + 32]);
    }

    while (gid < G) {
        const int nid = gid + stride;
        // Prefetch next group's rows (warp-uniform branch, no divergence).
        if (nid < G) {
            const float4* __restrict__ xr = x4 + (size_t)nid * (size_t)(P * F4);
            nxt[0] = __ldcs(&xr[0 * F4 + lane]);
            nxt[1] = __ldcs(&xr[0 * F4 + lane + 32]);
            nxt[2] = __ldcs(&xr[1 * F4 + lane]);
            nxt[3] = __ldcs(&xr[1 * F4 + lane + 32]);
            nxt[4] = __ldcs(&xr[2 * F4 + lane]);
            nxt[5] = __ldcs(&xr[2 * F4 + lane + 32]);
        }

        // Per-row partial dot products for the CURRENT group.
        float d0 = cur[0].x * w0.x + cur[0].y * w0.y + cur[0].z * w0.z + cur[0].w * w0.w
                 + cur[1].x * w1.x + cur[1].y * w1.y + cur[1].z * w1.z + cur[1].w * w1.w;
        float d1 = cur[2].x * w0.x + cur[2].y * w0.y + cur[2].z * w0.z + cur[2].w * w0.w
                 + cur[3].x * w1.x + cur[3].y * w1.y + cur[3].z * w1.z + cur[3].w * w1.w;
        float d2 = cur[4].x * w0.x + cur[4].y * w0.y + cur[4].z * w0.z + cur[4].w * w0.w
                 + cur[5].x * w1.x + cur[5].y * w1.y + cur[5].z * w1.z + cur[5].w * w1.w;

        // Warp butterfly reduce (all three dots share the butterfly passes).
        #pragma unroll
        for (int off = 16; off > 0; off >>= 1) {
            d0 += __shfl_xor_sync(0xffffffffu, d0, off);
            d1 += __shfl_xor_sync(0xffffffffu, d1, off);
            d2 += __shfl_xor_sync(0xffffffffu, d2, off);
        }

        // 3-way softmax (bias cancels; subtract max for stability).
        float m  = fmaxf(d0, fmaxf(d1, d2));
        float e0 = __expf(d0 - m);
        float e1 = __expf(d1 - m);
        float e2 = __expf(d2 - m);
        float inv = 1.0f / (e0 + e1 + e2);
        float a0 = e0 * inv, a1 = e1 * inv, a2 = e2 * inv;

        // Weighted sum of the three rows.
        float4 o0, o1;
        o0.x = cur[0].x * a0 + cur[2].x * a1 + cur[4].x * a2;
        o0.y = cur[0].y * a0 + cur[2].y * a1 + cur[4].y * a2;
        o0.z = cur[0].z * a0 + cur[2].z * a1 + cur[4].z * a2;
        o0.w = cur[0].w * a0 + cur[2].w * a1 + cur[4].w * a2;
        o1.x = cur[1].x * a0 + cur[3].x * a1 + cur[5].x * a2;
        o1.y = cur[1].y * a0 + cur[3].y * a1 + cur[5].y * a2;
        o1.z = cur[1].z * a0 + cur[3].z * a1 + cur[5].z * a2;
        o1.w = cur[1].w * a0 + cur[3].w * a1 + cur[5].w * a2;

        float4* __restrict__ op = reinterpret_cast<float4*>(out + (size_t)gid * F);
        __stcs(&op[lane],      o0);
        __stcs(&op[lane + 32], o1);

        // Rotate buffers and advance.
        #pragma unroll
        for (int i = 0; i < 6; i++) cur[i] = nxt[i];
        gid = nid;
    }
}

extern "C" void kernel_launch(void* const* d_in, const int* in_sizes, int n_in,
                              void* d_out, int out_size)
{
    const float* x = (const float*)d_in[0];   // batch_rep [196608, 256]
    const float* w = (const float*)d_in[1];   // W_weight  [1, 256]
    // d_in[2] = W_bias [1] — softmax-invariant, unused.
    float* out = (float*)d_out;               // [65536, 256]

    const int B = in_sizes[0] / F;            // 196608
    const int G = B / P;                      // 65536

    gap_kernel<<<GRID, THREADS>>>(x, w, out, G);
}

// round 4
// speedup vs baseline: 1.0015x; 1.0015x over previous
#include <cuda_runtime.h>
#include <cuda_bf16.h>
#include <cstdint>

// GraphAttentionPooling — 256-bit load/store version (sm_100 LDG.E.256).
//   x: [B=196608, F=256] f32, G=65536 groups of P=3 rows.
//   out[g,f] = sum_p softmax_p(dot(x[g,p,:],w))[p] * x[g,p,f]
//
// One warp per group. Lane l owns floats [8l, 8l+8) of each 256-float row:
// exactly one ld.global.v8.f32 per row (3 loads) and one st.global.v8.f32
// for the output row. Tests whether wider requests lift achieved DRAM BW
// past the ~6.2 TB/s plateau seen across R1-R3.

#define F 256
#define P 3
#define WARPS_PER_BLOCK 8
#define THREADS (WARPS_PER_BLOCK * 32)

// 256-bit global load (read-only path).
#define LDG256(d, ptr)                                                        \
    asm volatile("ld.global.nc.v8.f32 {%0,%1,%2,%3,%4,%5,%6,%7}, [%8];"       \
                 : "=f"(d[0]), "=f"(d[1]), "=f"(d[2]), "=f"(d[3]),            \
                   "=f"(d[4]), "=f"(d[5]), "=f"(d[6]), "=f"(d[7])             \
                 : "l"(ptr))

// 256-bit global store.
#define STG256(ptr, s)                                                        \
    asm volatile("st.global.v8.f32 [%0], {%1,%2,%3,%4,%5,%6,%7,%8};"          \
                 :: "l"(ptr),                                                 \
                    "f"(s[0]), "f"(s[1]), "f"(s[2]), "f"(s[3]),               \
                    "f"(s[4]), "f"(s[5]), "f"(s[6]), "f"(s[7])                \
                 : "memory")

__global__ __launch_bounds__(THREADS)
void gap_kernel(const float* __restrict__ x,
                const float* __restrict__ w,
                float* __restrict__ out,
                int G)
{
    const int gid  = (blockIdx.x * WARPS_PER_BLOCK) + (threadIdx.x >> 5);
    const int lane = threadIdx.x & 31;
    if (gid >= G) return;

    const float* xr = x + (size_t)gid * (size_t)(P * F) + lane * 8;

    // Front-batch all global loads: 3 LDG.256 + 1 weight LDG.256.
    float r0[8], r1[8], r2[8], wv[8];
    LDG256(r0, xr);
    LDG256(r1, xr + F);
    LDG256(r2, xr + 2 * F);
    LDG256(wv, w + lane * 8);

    // Per-row partial dot products over this lane's 8 elements.
    float d0 = 0.f, d1 = 0.f, d2 = 0.f;
    #pragma unroll
    for (int i = 0; i < 8; i++) {
        d0 = fmaf(r0[i], wv[i], d0);
        d1 = fmaf(r1[i], wv[i], d1);
        d2 = fmaf(r2[i], wv[i], d2);
    }

    // Warp butterfly reduce (all three dots share the butterfly passes).
    #pragma unroll
    for (int off = 16; off > 0; off >>= 1) {
        d0 += __shfl_xor_sync(0xffffffffu, d0, off);
        d1 += __shfl_xor_sync(0xffffffffu, d1, off);
        d2 += __shfl_xor_sync(0xffffffffu, d2, off);
    }

    // 3-way softmax (bias cancels; subtract max for stability).
    float m  = fmaxf(d0, fmaxf(d1, d2));
    float e0 = __expf(d0 - m);
    float e1 = __expf(d1 - m);
    float e2 = __expf(d2 - m);
    float inv = 1.0f / (e0 + e1 + e2);
    float a0 = e0 * inv, a1 = e1 * inv, a2 = e2 * inv;

    // Weighted sum of the three rows -> one STG.256.
    float o[8];
    #pragma unroll
    for (int i = 0; i < 8; i++)
        o[i] = fmaf(r0[i], a0, fmaf(r1[i], a1, r2[i] * a2));

    float* op = out + (size_t)gid * F + lane * 8;
    STG256(op, o);
}

extern "C" void kernel_launch(void* const* d_in, const int* in_sizes, int n_in,
                              void* d_out, int out_size)
{
    const float* x = (const float*)d_in[0];   // batch_rep [196608, 256]
    const float* w = (const float*)d_in[1];   // W_weight  [1, 256]
    // d_in[2] = W_bias [1] — softmax-invariant, unused.
    float* out = (float*)d_out;               // [65536, 256]

    const int B = in_sizes[0] / F;            // 196608
    const int G = B / P;                      // 65536

    const int blocks = (G + WARPS_PER_BLOCK - 1) / WARPS_PER_BLOCK;
    gap_kernel<<<blocks, THREADS>>>(x, w, out, G);
}